// round 16
// baseline (speedup 1.0000x reference)
#include <cuda_runtime.h>
#include <cuda_bf16.h>
#include <cstdint>

// ---------------- problem constants ----------------
static constexpr int BATCH  = 4;
static constexpr int SEQ    = 4096;
static constexpr int DMODEL = 1024;
static constexpr int STATE  = 256;
static constexpr int MTOT   = BATCH * SEQ;     // 16384
static constexpr int NCHUNK = 256;
static constexpr int CLEN   = SEQ / NCHUNK;    // 16

// ---------------- device scratch ----------------
__device__ float          g_Bu[(size_t)MTOT * STATE];        // 16 MB
__device__ __nv_bfloat16  g_Bw_hi[STATE * DMODEL];
__device__ __nv_bfloat16  g_Bw_lo[STATE * DMODEL];
__device__ __nv_bfloat16  g_Cw_hi[DMODEL * STATE];
__device__ __nv_bfloat16  g_Cw_lo[DMODEL * STATE];
__device__ __nv_bfloat16  g_hs_hi[(size_t)MTOT * STATE];     // 8 MB
__device__ __nv_bfloat16  g_hs_lo[(size_t)MTOT * STATE];     // 8 MB
__device__ float          g_F[BATCH * NCHUNK * STATE];       // 256 KB (L2-resident)
__device__ float          g_lam[STATE];                      // sigmoid(log_lambda)

// ---------------- helpers ----------------
__device__ __forceinline__ uint32_t smem_u32(const void* p) {
    uint32_t a;
    asm("{ .reg .u64 t; cvta.to.shared.u64 t, %1; cvt.u32.u64 %0, t; }"
        : "=r"(a) : "l"(p));
    return a;
}
__device__ __forceinline__ uint32_t swz(uint32_t b) { return b ^ ((b >> 3) & 0x70); }

#define CP16(saddr, gptr) \
    asm volatile("cp.async.cg.shared.global [%0], [%1], 16;" \
                 :: "r"(saddr), "l"(gptr) : "memory")
#define CP_COMMIT() asm volatile("cp.async.commit_group;" ::: "memory")
#define CP_WAIT0()  asm volatile("cp.async.wait_group 0;" ::: "memory")
#define LDM4(r, addr) \
    asm volatile("ldmatrix.sync.aligned.m8n8.x4.shared.b16 {%0,%1,%2,%3}, [%4];" \
        : "=r"((r)[0]), "=r"((r)[1]), "=r"((r)[2]), "=r"((r)[3]) : "r"(addr))
#define MMA16816(d, a, b0, b1) \
    asm volatile("mma.sync.aligned.m16n8k16.row.col.f32.bf16.bf16.f32 " \
        "{%0,%1,%2,%3}, {%4,%5,%6,%7}, {%8,%9}, {%0,%1,%2,%3};" \
        : "+f"((d)[0]), "+f"((d)[1]), "+f"((d)[2]), "+f"((d)[3]) \
        : "r"((a)[0]), "r"((a)[1]), "r"((a)[2]), "r"((a)[3]), \
          "r"(b0), "r"(b1))

__device__ __forceinline__ void split_bf16(float x, unsigned short& h, unsigned short& l) {
    __nv_bfloat16 bh = __float2bfloat16_rn(x);
    float r = x - __bfloat162float(bh);
    __nv_bfloat16 bl = __float2bfloat16_rn(r);
    h = reinterpret_cast<unsigned short&>(bh);
    l = reinterpret_cast<unsigned short&>(bl);
}

// One launch: split both weight matrices + precompute lam table.
__global__ void __launch_bounds__(256)
split_weights(const float4* __restrict__ Bw, ushort4* __restrict__ Bh4, ushort4* __restrict__ Bl4,
              const float4* __restrict__ Cw, ushort4* __restrict__ Ch4, ushort4* __restrict__ Cl4,
              int n4each, const float* __restrict__ logl)
{
    const int gi = blockIdx.x * 256 + threadIdx.x;
    if (gi < STATE) g_lam[gi] = 1.f / (1.f + expf(-logl[gi]));

    int i = gi;
    const float4* src; ushort4 *dh, *dl;
    if (i < n4each) { src = Bw; dh = Bh4; dl = Bl4; }
    else            { src = Cw; dh = Ch4; dl = Cl4; i -= n4each; if (i >= n4each) return; }
    float4 v = src[i];
    ushort4 h, l;
    split_bf16(v.x, h.x, l.x);
    split_bf16(v.y, h.y, l.y);
    split_bf16(v.z, h.z, l.z);
    split_bf16(v.w, h.w, l.w);
    dh[i] = h;
    dl[i] = l;
}

// ---------------------------------------------------------------------------
// bf16x3 HMMA GEMM, CTA tile 128x256, 256 threads / 8 warps (warp tile 64x64),
// BK=64, double-buffered cp.async, single __syncthreads per chunk.
// A_FP32: fp32-A staging (LDG->split->STS, two halves)   [GEMM1]
// FUSE_F: epilogue also emits chunk-final states g_F      [GEMM1, CLEN=16]
// EPI:    fused D*U skip (U loads elided when D pair==0)  [GEMM2]
// ---------------------------------------------------------------------------
template<int KDIM, bool A_FP32, bool EPI, bool FUSE_F>
__global__ void __launch_bounds__(256, 1)
gemm_128x256(const float* __restrict__ Af,
             const __nv_bfloat16* __restrict__ Ah, const __nv_bfloat16* __restrict__ Al,
             const __nv_bfloat16* __restrict__ Bh, const __nv_bfloat16* __restrict__ Bl,
             float* __restrict__ C, int Ntot,
             const float* __restrict__ Dv, const float* __restrict__ U,
             const float* __restrict__ LamV)
{
    constexpr int BK    = 64;
    constexpr int NCH   = KDIM / BK;
    constexpr int TA    = 128 * BK * 2;        // 16 KB
    constexpr int SB_HI = 2 * TA;              // 32 KB
    constexpr int TB    = 256 * BK * 2;        // 32 KB
    constexpr int SB_LO = SB_HI + TB;
    constexpr int STAGE = SB_LO + TB;          // 96 KB

    extern __shared__ char smem[];
    __shared__ float s_lam[STATE];
    const uint32_t sbase = smem_u32(smem);

    const int tid  = threadIdx.x;
    const int wid  = tid >> 5;
    const int lane = tid & 31;
    const int wm   = (wid >> 2) * 64;
    const int wn   = (wid & 3) * 64;
    const size_t m0 = (size_t)blockIdx.y * 128;
    const size_t n0 = (size_t)blockIdx.x * 256;

    if (FUSE_F) s_lam[tid] = LamV[tid];        // visible after first mainloop sync

    float acc[4][8][4];
#pragma unroll
    for (int i = 0; i < 4; i++)
#pragma unroll
        for (int j = 0; j < 8; j++)
#pragma unroll
            for (int k = 0; k < 4; k++) acc[i][j][k] = 0.f;

    auto load_B = [&](int c) {
        const uint32_t sd = sbase + (c & 1) * STAGE;
        const int k0 = c * BK;
#pragma unroll
        for (int t = 0; t < 8; t++) {
            const int idx = t * 256 + tid;
            const int row = idx >> 3;
            const int c16 = idx & 7;
            const uint32_t sw = swz(row * 128 + c16 * 16);
            const size_t gb = (n0 + row) * (size_t)KDIM + k0 + c16 * 8;
            CP16(sd + SB_HI + sw, Bh + gb);
            CP16(sd + SB_LO + sw, Bl + gb);
        }
    };
    auto load_A_bf16 = [&](int c) {
        const uint32_t sd = sbase + (c & 1) * STAGE;
        const int k0 = c * BK;
#pragma unroll
        for (int t = 0; t < 4; t++) {
            const int idx = t * 256 + tid;
            const int row = idx >> 3;
            const int c16 = idx & 7;
            const uint32_t sw = swz(row * 128 + c16 * 16);
            const size_t ga = (m0 + row) * (size_t)KDIM + k0 + c16 * 8;
            CP16(sd + sw,      Ah + ga);
            CP16(sd + TA + sw, Al + ga);
        }
    };

    // fp32-A staging, HALF a tile at a time (16 regs)
    float4 areg[4];
    auto lda_h = [&](int c, int h) {
        const int k0 = c * BK;
#pragma unroll
        for (int t = 0; t < 4; t++) {
            const int idx = (h * 4 + t) * 256 + tid;
            const int row = idx >> 4;
            const int c4  = idx & 15;
            areg[t] = *(const float4*)(Af + (m0 + row) * (size_t)KDIM + k0 + c4 * 4);
        }
    };
    auto sta_h = [&](int c, int h) {
        const uint32_t stg = (c & 1) * STAGE;
#pragma unroll
        for (int t = 0; t < 4; t++) {
            const int idx = (h * 4 + t) * 256 + tid;
            const int row = idx >> 4;
            const int c4  = idx & 15;
            ushort4 hh, ll;
            split_bf16(areg[t].x, hh.x, ll.x);
            split_bf16(areg[t].y, hh.y, ll.y);
            split_bf16(areg[t].z, hh.z, ll.z);
            split_bf16(areg[t].w, hh.w, ll.w);
            const uint32_t sw = swz(row * 128 + c4 * 8);
            *(ushort4*)(smem + stg + sw)      = hh;
            *(ushort4*)(smem + stg + TA + sw) = ll;
        }
    };

    // prologue: stage 0
    load_B(0);
    if (!A_FP32) load_A_bf16(0);
    CP_COMMIT();
    if (A_FP32) { lda_h(0, 0); sta_h(0, 0); lda_h(0, 1); sta_h(0, 1); }

    const int j    = lane >> 3;
    const int r8   = lane & 7;
    const int rowa = wm + (j & 1) * 8 + r8;
    const int rowb = wn + (j & 1) * 8 + r8;
    const int colq = (j >> 1) * 16;

    auto compute_kk = [&](uint32_t sd, int kk) {
        const int colb = kk * 32 + colq;
        uint32_t ah[4][4], al[4][4];
#pragma unroll
        for (int mf = 0; mf < 4; mf++) {
            const uint32_t off = swz((rowa + mf * 16) * 128 + colb);
            LDM4(ah[mf], sd + off);
            LDM4(al[mf], sd + TA + off);
        }
#pragma unroll
        for (int nf4 = 0; nf4 < 4; nf4++) {
            const uint32_t offb = swz((rowb + nf4 * 16) * 128 + colb);
            uint32_t r[4], s[4];
            LDM4(r, sd + SB_HI + offb);
            LDM4(s, sd + SB_LO + offb);
#pragma unroll
            for (int mf = 0; mf < 4; mf++) {
                MMA16816(acc[mf][nf4 * 2],     ah[mf], r[0], r[2]);
                MMA16816(acc[mf][nf4 * 2],     ah[mf], s[0], s[2]);
                MMA16816(acc[mf][nf4 * 2],     al[mf], r[0], r[2]);
                MMA16816(acc[mf][nf4 * 2 + 1], ah[mf], r[1], r[3]);
                MMA16816(acc[mf][nf4 * 2 + 1], ah[mf], s[1], s[3]);
                MMA16816(acc[mf][nf4 * 2 + 1], al[mf], r[1], r[3]);
            }
        }
    };

    for (int c = 0; c < NCH; c++) {
        CP_WAIT0();
        __syncthreads();

        const bool more = (c + 1 < NCH);
        if (more) {
            load_B(c + 1);
            if (!A_FP32) load_A_bf16(c + 1);
            CP_COMMIT();
            if (A_FP32) lda_h(c + 1, 0);
        }

        const uint32_t sd = sbase + (c & 1) * STAGE;
        compute_kk(sd, 0);
        compute_kk(sd, 1);
        if (A_FP32 && more) { sta_h(c + 1, 0); lda_h(c + 1, 1); }
        compute_kk(sd, 2);
        compute_kk(sd, 3);
        if (A_FP32 && more) sta_h(c + 1, 1);
    }

    // ---- epilogue: C stores (+ optional fused chunk-final F) ----
    const int rr = lane >> 2;
    const int cc = (lane & 3) * 2;
#pragma unroll
    for (int mf = 0; mf < 4; mf++) {
        const size_t mA = m0 + wm + mf * 16 + rr;
        const size_t mB = mA + 8;
#pragma unroll
        for (int nf = 0; nf < 8; nf++) {
            const size_t n = n0 + wn + nf * 8 + cc;
            float2 v0 = make_float2(acc[mf][nf][0], acc[mf][nf][1]);
            float2 v1 = make_float2(acc[mf][nf][2], acc[mf][nf][3]);
            if (EPI) {
                const float2 d2 = *(const float2*)(Dv + n);
                if (d2.x != 0.f || d2.y != 0.f) {   // D==0 -> skip U reads
                    const float2 uA = *(const float2*)(U + mA * (size_t)Ntot + n);
                    const float2 uB = *(const float2*)(U + mB * (size_t)Ntot + n);
                    v0.x = fmaf(d2.x, uA.x, v0.x);
                    v0.y = fmaf(d2.y, uA.y, v0.y);
                    v1.x = fmaf(d2.x, uB.x, v1.x);
                    v1.y = fmaf(d2.y, uB.y, v1.y);
                }
            }
            *(float2*)(C + mA * (size_t)Ntot + n) = v0;
            *(float2*)(C + mB * (size_t)Ntot + n) = v1;
        }
    }

    if (FUSE_F) {
        // CLEN=16: one 16-row chunk per mf fragment (rows rr and rr+8).
        // F[ch, n] = reduce_rr( (acc_rr * lam^8 + acc_rr8) * lam^(7-rr) )
        const int b   = (int)(m0 >> 12);                 // m0 / SEQ
        const int ch0 = (int)((m0 & (SEQ - 1)) >> 4);    // chunk of CTA row 0
#pragma unroll
        for (int mf = 0; mf < 4; mf++) {
            const int chg = ch0 + (wm >> 4) + mf;
#pragma unroll
            for (int nf = 0; nf < 8; nf++) {
#pragma unroll
                for (int k2 = 0; k2 < 2; k2++) {
                    const int n = wn + nf * 8 + cc + k2;
                    const float lam = s_lam[n];
                    const float l2 = lam * lam, l4 = l2 * l2, l8 = l4 * l4;
                    float w = 1.f;
#pragma unroll
                    for (int i = 0; i < 7; i++)
                        if (i < 7 - rr) w *= lam;
                    float part = fmaf(acc[mf][nf][k2], l8, acc[mf][nf][k2 + 2]);
                    part *= w;
                    part += __shfl_xor_sync(0xffffffffu, part, 4);
                    part += __shfl_xor_sync(0xffffffffu, part, 8);
                    part += __shfl_xor_sync(0xffffffffu, part, 16);
                    if (rr == 0)
                        g_F[((size_t)b * NCHUNK + chg) * STATE + n] = part;
                }
            }
        }
    }
}

// ---------------- scan apply (self-contained: recomputes its entry state) ---
// One block per (batch, chunk); 64 threads x 4 states (float4).
// Entry state H = sum_{c<ch} lamL^{ch-1-c} * F[c]: a weighted sum whose only
// loop-carried dependency is w *= lamL (FMUL chain); F loads pipeline freely
// out of L2 (g_F is 256 KB, resident). Then the 16-step recurrence + hi/lo.
__global__ void __launch_bounds__(64)
scan_apply()
{
    const int b  = blockIdx.x;
    const int ch = blockIdx.y;
    const int n  = threadIdx.x * 4;

    const float4 lam4 = *(const float4*)(g_lam + n);
    float4 lamL = lam4;
#pragma unroll
    for (int i = 0; i < 4; i++) {              // lam^16  (CLEN = 16)
        lamL.x *= lamL.x; lamL.y *= lamL.y;
        lamL.z *= lamL.z; lamL.w *= lamL.w;
    }

    // entry state from chunk finals (descending weight accumulation)
    float4 h = make_float4(0.f, 0.f, 0.f, 0.f);
    float4 w = make_float4(1.f, 1.f, 1.f, 1.f);
    const float4* Fb = (const float4*)(g_F + (size_t)b * NCHUNK * STATE + n);
    for (int c = ch - 1; c >= 0; c--) {
        const float4 f = Fb[c * (STATE / 4)];
        h.x = fmaf(w.x, f.x, h.x);
        h.y = fmaf(w.y, f.y, h.y);
        h.z = fmaf(w.z, f.z, h.z);
        h.w = fmaf(w.w, f.w, h.w);
        w.x *= lamL.x; w.y *= lamL.y;
        w.z *= lamL.z; w.w *= lamL.w;
    }

    const size_t m0 = (size_t)b * SEQ + (size_t)ch * CLEN;
    const float4* p = (const float4*)(g_Bu + m0 * STATE + n);
    unsigned short* oh = (unsigned short*)g_hs_hi + m0 * STATE + n;
    unsigned short* ol = (unsigned short*)g_hs_lo + m0 * STATE + n;

#pragma unroll
    for (int t = 0; t < CLEN; t++) {
        const float4 v = p[t * (STATE / 4)];
        h.x = fmaf(lam4.x, h.x, v.x);
        h.y = fmaf(lam4.y, h.y, v.y);
        h.z = fmaf(lam4.z, h.z, v.z);
        h.w = fmaf(lam4.w, h.w, v.w);
        ushort4 hh, ll;
        split_bf16(h.x, hh.x, ll.x);
        split_bf16(h.y, hh.y, ll.y);
        split_bf16(h.z, hh.z, ll.z);
        split_bf16(h.w, hh.w, ll.w);
        *(ushort4*)(oh + (size_t)t * STATE) = hh;
        *(ushort4*)(ol + (size_t)t * STATE) = ll;
    }
}

// ---------------- launch ----------------
extern "C" void kernel_launch(void* const* d_in, const int* in_sizes, int n_in,
                              void* d_out, int out_size)
{
    const float* u          = (const float*)d_in[0];
    const float* log_lambda = (const float*)d_in[1];
    const float* B_w        = (const float*)d_in[2];
    const float* C_w        = (const float*)d_in[3];
    const float* Dvec       = (const float*)d_in[4];
    float* y = (float*)d_out;

    float *Bu, *lam;
    __nv_bfloat16 *Bw_hi, *Bw_lo, *Cw_hi, *Cw_lo, *hs_hi, *hs_lo;
    cudaGetSymbolAddress((void**)&Bu,    g_Bu);
    cudaGetSymbolAddress((void**)&lam,   g_lam);
    cudaGetSymbolAddress((void**)&Bw_hi, g_Bw_hi);
    cudaGetSymbolAddress((void**)&Bw_lo, g_Bw_lo);
    cudaGetSymbolAddress((void**)&Cw_hi, g_Cw_hi);
    cudaGetSymbolAddress((void**)&Cw_lo, g_Cw_lo);
    cudaGetSymbolAddress((void**)&hs_hi, g_hs_hi);
    cudaGetSymbolAddress((void**)&hs_lo, g_hs_lo);

    const int DSMEM = 2 * (2 * 128 * 64 * 2 + 2 * 256 * 64 * 2);   // 196608
    cudaFuncSetAttribute(gemm_128x256<DMODEL, true, false, true>,
                         cudaFuncAttributeMaxDynamicSharedMemorySize, DSMEM);
    cudaFuncSetAttribute(gemm_128x256<STATE, false, true, false>,
                         cudaFuncAttributeMaxDynamicSharedMemorySize, DSMEM);

    // launch 0: split both weight matrices + lam table
    {
        int n4w = STATE * DMODEL / 4;
        split_weights<<<(2 * n4w + 255) / 256, 256>>>(
            (const float4*)B_w, (ushort4*)Bw_hi, (ushort4*)Bw_lo,
            (const float4*)C_w, (ushort4*)Cw_hi, (ushort4*)Cw_lo,
            n4w, log_lambda);
    }

    // launch 1: GEMM1  Bu = u . B_w^T  (K=1024) + fused chunk-finals -> g_F
    gemm_128x256<DMODEL, true, false, true><<<dim3(1, MTOT / 128), 256, DSMEM>>>(
        u, nullptr, nullptr, Bw_hi, Bw_lo, Bu, STATE, nullptr, nullptr, lam);

    // launch 2: apply scan -> hs (computes its own entry state from g_F)
    scan_apply<<<dim3(BATCH, NCHUNK), 64>>>();

    // launch 3: GEMM2  y = hs . C_w^T + D*u  (K=256)
    gemm_128x256<STATE, false, true, false><<<dim3(DMODEL / 256, MTOT / 128), 256, DSMEM>>>(
        nullptr, hs_hi, hs_lo, Cw_hi, Cw_lo, y, DMODEL, Dvec, u, nullptr);
}

// round 17
// speedup vs baseline: 1.0446x; 1.0446x over previous
#include <cuda_runtime.h>
#include <cuda_bf16.h>
#include <cstdint>

// ---------------- problem constants ----------------
static constexpr int BATCH  = 4;
static constexpr int SEQ    = 4096;
static constexpr int DMODEL = 1024;
static constexpr int STATE  = 256;
static constexpr int MTOT   = BATCH * SEQ;     // 16384
static constexpr int NCHUNK = 256;
static constexpr int CLEN   = SEQ / NCHUNK;    // 16

// ---------------- device scratch ----------------
__device__ float          g_Bu[(size_t)MTOT * STATE];        // 16 MB
__device__ __nv_bfloat16  g_Bw_hi[STATE * DMODEL];
__device__ __nv_bfloat16  g_Bw_lo[STATE * DMODEL];
__device__ __nv_bfloat16  g_Cw_hi[DMODEL * STATE];
__device__ __nv_bfloat16  g_Cw_lo[DMODEL * STATE];
__device__ __nv_bfloat16  g_hs_hi[(size_t)MTOT * STATE];     // 8 MB
__device__ __nv_bfloat16  g_hs_lo[(size_t)MTOT * STATE];     // 8 MB
__device__ float          g_F[BATCH * NCHUNK * STATE];       // 1 MB
__device__ float          g_H[BATCH * NCHUNK * STATE];       // 1 MB
__device__ float          g_lam[STATE];                      // sigmoid(log_lambda)
__device__ int            g_Dnz;                             // any(D != 0)

// ---------------- helpers ----------------
__device__ __forceinline__ uint32_t smem_u32(const void* p) {
    uint32_t a;
    asm("{ .reg .u64 t; cvta.to.shared.u64 t, %1; cvt.u32.u64 %0, t; }"
        : "=r"(a) : "l"(p));
    return a;
}
__device__ __forceinline__ uint32_t swz(uint32_t b) { return b ^ ((b >> 3) & 0x70); }

#define CP16(saddr, gptr) \
    asm volatile("cp.async.cg.shared.global [%0], [%1], 16;" \
                 :: "r"(saddr), "l"(gptr) : "memory")
#define CP_COMMIT() asm volatile("cp.async.commit_group;" ::: "memory")
#define CP_WAIT0()  asm volatile("cp.async.wait_group 0;" ::: "memory")
#define LDM4(r, addr) \
    asm volatile("ldmatrix.sync.aligned.m8n8.x4.shared.b16 {%0,%1,%2,%3}, [%4];" \
        : "=r"((r)[0]), "=r"((r)[1]), "=r"((r)[2]), "=r"((r)[3]) : "r"(addr))
#define MMA16816(d, a, b0, b1) \
    asm volatile("mma.sync.aligned.m16n8k16.row.col.f32.bf16.bf16.f32 " \
        "{%0,%1,%2,%3}, {%4,%5,%6,%7}, {%8,%9}, {%0,%1,%2,%3};" \
        : "+f"((d)[0]), "+f"((d)[1]), "+f"((d)[2]), "+f"((d)[3]) \
        : "r"((a)[0]), "r"((a)[1]), "r"((a)[2]), "r"((a)[3]), \
          "r"(b0), "r"(b1))

__device__ __forceinline__ void split_bf16(float x, unsigned short& h, unsigned short& l) {
    __nv_bfloat16 bh = __float2bfloat16_rn(x);
    float r = x - __bfloat162float(bh);
    __nv_bfloat16 bl = __float2bfloat16_rn(r);
    h = reinterpret_cast<unsigned short&>(bh);
    l = reinterpret_cast<unsigned short&>(bl);
}

// One launch: split both weight matrices + lam table + D-nonzero flag.
__global__ void __launch_bounds__(256)
split_weights(const float4* __restrict__ Bw, ushort4* __restrict__ Bh4, ushort4* __restrict__ Bl4,
              const float4* __restrict__ Cw, ushort4* __restrict__ Ch4, ushort4* __restrict__ Cl4,
              int n4each, const float* __restrict__ logl, const float* __restrict__ Dv)
{
    const int gi = blockIdx.x * 256 + threadIdx.x;
    if (gi < STATE) g_lam[gi] = 1.f / (1.f + expf(-logl[gi]));
    if (gi == 0) g_Dnz = 0;          // reset each call (deterministic)
    if (gi < DMODEL) {
        if (Dv[gi] != 0.f) atomicExch(&g_Dnz, 1);
    }

    int i = gi;
    const float4* src; ushort4 *dh, *dl;
    if (i < n4each) { src = Bw; dh = Bh4; dl = Bl4; }
    else            { src = Cw; dh = Ch4; dl = Cl4; i -= n4each; if (i >= n4each) return; }
    float4 v = src[i];
    ushort4 h, l;
    split_bf16(v.x, h.x, l.x);
    split_bf16(v.y, h.y, l.y);
    split_bf16(v.z, h.z, l.z);
    split_bf16(v.w, h.w, l.w);
    dh[i] = h;
    dl[i] = l;
}

// ---------------------------------------------------------------------------
// bf16x3 HMMA GEMM, CTA tile 128x256, 256 threads / 8 warps (warp tile 64x64),
// BK=64, double-buffered cp.async, single __syncthreads per chunk.
// A_FP32: fp32-A staging (LDG->split->STS, two halves)   [GEMM1]
// FUSE_F: epilogue also emits chunk-final states g_F      [GEMM1, CLEN=16]
// EPI:    fused D*U skip, gated by uniform g_Dnz flag     [GEMM2]
// ---------------------------------------------------------------------------
template<int KDIM, bool A_FP32, bool EPI, bool FUSE_F>
__global__ void __launch_bounds__(256, 1)
gemm_128x256(const float* __restrict__ Af,
             const __nv_bfloat16* __restrict__ Ah, const __nv_bfloat16* __restrict__ Al,
             const __nv_bfloat16* __restrict__ Bh, const __nv_bfloat16* __restrict__ Bl,
             float* __restrict__ C, int Ntot,
             const float* __restrict__ Dv, const float* __restrict__ U,
             const float* __restrict__ LamV)
{
    constexpr int BK    = 64;
    constexpr int NCH   = KDIM / BK;
    constexpr int TA    = 128 * BK * 2;        // 16 KB
    constexpr int SB_HI = 2 * TA;              // 32 KB
    constexpr int TB    = 256 * BK * 2;        // 32 KB
    constexpr int SB_LO = SB_HI + TB;
    constexpr int STAGE = SB_LO + TB;          // 96 KB

    extern __shared__ char smem[];
    __shared__ float s_lam[STATE];
    const uint32_t sbase = smem_u32(smem);

    const int tid  = threadIdx.x;
    const int wid  = tid >> 5;
    const int lane = tid & 31;
    const int wm   = (wid >> 2) * 64;
    const int wn   = (wid & 3) * 64;
    const size_t m0 = (size_t)blockIdx.y * 128;
    const size_t n0 = (size_t)blockIdx.x * 256;

    if (FUSE_F) s_lam[tid] = LamV[tid];        // visible after first mainloop sync

    float acc[4][8][4];
#pragma unroll
    for (int i = 0; i < 4; i++)
#pragma unroll
        for (int j = 0; j < 8; j++)
#pragma unroll
            for (int k = 0; k < 4; k++) acc[i][j][k] = 0.f;

    auto load_B = [&](int c) {
        const uint32_t sd = sbase + (c & 1) * STAGE;
        const int k0 = c * BK;
#pragma unroll
        for (int t = 0; t < 8; t++) {
            const int idx = t * 256 + tid;
            const int row = idx >> 3;
            const int c16 = idx & 7;
            const uint32_t sw = swz(row * 128 + c16 * 16);
            const size_t gb = (n0 + row) * (size_t)KDIM + k0 + c16 * 8;
            CP16(sd + SB_HI + sw, Bh + gb);
            CP16(sd + SB_LO + sw, Bl + gb);
        }
    };
    auto load_A_bf16 = [&](int c) {
        const uint32_t sd = sbase + (c & 1) * STAGE;
        const int k0 = c * BK;
#pragma unroll
        for (int t = 0; t < 4; t++) {
            const int idx = t * 256 + tid;
            const int row = idx >> 3;
            const int c16 = idx & 7;
            const uint32_t sw = swz(row * 128 + c16 * 16);
            const size_t ga = (m0 + row) * (size_t)KDIM + k0 + c16 * 8;
            CP16(sd + sw,      Ah + ga);
            CP16(sd + TA + sw, Al + ga);
        }
    };

    // fp32-A staging, HALF a tile at a time (16 regs)
    float4 areg[4];
    auto lda_h = [&](int c, int h) {
        const int k0 = c * BK;
#pragma unroll
        for (int t = 0; t < 4; t++) {
            const int idx = (h * 4 + t) * 256 + tid;
            const int row = idx >> 4;
            const int c4  = idx & 15;
            areg[t] = *(const float4*)(Af + (m0 + row) * (size_t)KDIM + k0 + c4 * 4);
        }
    };
    auto sta_h = [&](int c, int h) {
        const uint32_t stg = (c & 1) * STAGE;
#pragma unroll
        for (int t = 0; t < 4; t++) {
            const int idx = (h * 4 + t) * 256 + tid;
            const int row = idx >> 4;
            const int c4  = idx & 15;
            ushort4 hh, ll;
            split_bf16(areg[t].x, hh.x, ll.x);
            split_bf16(areg[t].y, hh.y, ll.y);
            split_bf16(areg[t].z, hh.z, ll.z);
            split_bf16(areg[t].w, hh.w, ll.w);
            const uint32_t sw = swz(row * 128 + c4 * 8);
            *(ushort4*)(smem + stg + sw)      = hh;
            *(ushort4*)(smem + stg + TA + sw) = ll;
        }
    };

    // prologue: stage 0
    load_B(0);
    if (!A_FP32) load_A_bf16(0);
    CP_COMMIT();
    if (A_FP32) { lda_h(0, 0); sta_h(0, 0); lda_h(0, 1); sta_h(0, 1); }

    const int j    = lane >> 3;
    const int r8   = lane & 7;
    const int rowa = wm + (j & 1) * 8 + r8;
    const int rowb = wn + (j & 1) * 8 + r8;
    const int colq = (j >> 1) * 16;

    auto compute_kk = [&](uint32_t sd, int kk) {
        const int colb = kk * 32 + colq;
        uint32_t ah[4][4], al[4][4];
#pragma unroll
        for (int mf = 0; mf < 4; mf++) {
            const uint32_t off = swz((rowa + mf * 16) * 128 + colb);
            LDM4(ah[mf], sd + off);
            LDM4(al[mf], sd + TA + off);
        }
#pragma unroll
        for (int nf4 = 0; nf4 < 4; nf4++) {
            const uint32_t offb = swz((rowb + nf4 * 16) * 128 + colb);
            uint32_t r[4], s[4];
            LDM4(r, sd + SB_HI + offb);
            LDM4(s, sd + SB_LO + offb);
#pragma unroll
            for (int mf = 0; mf < 4; mf++) {
                MMA16816(acc[mf][nf4 * 2],     ah[mf], r[0], r[2]);
                MMA16816(acc[mf][nf4 * 2],     ah[mf], s[0], s[2]);
                MMA16816(acc[mf][nf4 * 2],     al[mf], r[0], r[2]);
                MMA16816(acc[mf][nf4 * 2 + 1], ah[mf], r[1], r[3]);
                MMA16816(acc[mf][nf4 * 2 + 1], ah[mf], s[1], s[3]);
                MMA16816(acc[mf][nf4 * 2 + 1], al[mf], r[1], r[3]);
            }
        }
    };

    for (int c = 0; c < NCH; c++) {
        CP_WAIT0();
        __syncthreads();

        const bool more = (c + 1 < NCH);
        if (more) {
            load_B(c + 1);
            if (!A_FP32) load_A_bf16(c + 1);
            CP_COMMIT();
            if (A_FP32) lda_h(c + 1, 0);
        }

        const uint32_t sd = sbase + (c & 1) * STAGE;
        compute_kk(sd, 0);
        compute_kk(sd, 1);
        if (A_FP32 && more) { sta_h(c + 1, 0); lda_h(c + 1, 1); }
        compute_kk(sd, 2);
        compute_kk(sd, 3);
        if (A_FP32 && more) sta_h(c + 1, 1);
    }

    // ---- epilogue ----
    const int rr = lane >> 2;
    const int cc = (lane & 3) * 2;
    const bool dnz = EPI ? (g_Dnz != 0) : false;   // uniform, loaded once
#pragma unroll
    for (int mf = 0; mf < 4; mf++) {
        const size_t mA = m0 + wm + mf * 16 + rr;
        const size_t mB = mA + 8;
#pragma unroll
        for (int nf = 0; nf < 8; nf++) {
            const size_t n = n0 + wn + nf * 8 + cc;
            float2 v0 = make_float2(acc[mf][nf][0], acc[mf][nf][1]);
            float2 v1 = make_float2(acc[mf][nf][2], acc[mf][nf][3]);
            if (EPI && dnz) {
                const float2 d2 = *(const float2*)(Dv + n);
                const float2 uA = *(const float2*)(U + mA * (size_t)Ntot + n);
                const float2 uB = *(const float2*)(U + mB * (size_t)Ntot + n);
                v0.x = fmaf(d2.x, uA.x, v0.x);
                v0.y = fmaf(d2.y, uA.y, v0.y);
                v1.x = fmaf(d2.x, uB.x, v1.x);
                v1.y = fmaf(d2.y, uB.y, v1.y);
            }
            *(float2*)(C + mA * (size_t)Ntot + n) = v0;
            *(float2*)(C + mB * (size_t)Ntot + n) = v1;
        }
    }

    if (FUSE_F) {
        // CLEN=16: one 16-row chunk per mf fragment (rows rr and rr+8).
        // F[ch, n] = reduce_rr( (acc_rr * lam^8 + acc_rr8) * lam^(7-rr) )
        const int b   = (int)(m0 >> 12);
        const int ch0 = (int)((m0 & (SEQ - 1)) >> 4);
#pragma unroll
        for (int mf = 0; mf < 4; mf++) {
            const int chg = ch0 + (wm >> 4) + mf;
#pragma unroll
            for (int nf = 0; nf < 8; nf++) {
#pragma unroll
                for (int k2 = 0; k2 < 2; k2++) {
                    const int n = wn + nf * 8 + cc + k2;
                    const float lam = s_lam[n];
                    const float l2 = lam * lam, l4 = l2 * l2, l8 = l4 * l4;
                    float w = 1.f;
#pragma unroll
                    for (int i = 0; i < 7; i++)
                        if (i < 7 - rr) w *= lam;
                    float part = fmaf(acc[mf][nf][k2], l8, acc[mf][nf][k2 + 2]);
                    part *= w;
                    part += __shfl_xor_sync(0xffffffffu, part, 4);
                    part += __shfl_xor_sync(0xffffffffu, part, 8);
                    part += __shfl_xor_sync(0xffffffffu, part, 16);
                    if (rr == 0)
                        g_F[((size_t)b * NCHUNK + chg) * STATE + n] = part;
                }
            }
        }
    }
}

// ---------------- remaining scan phases ----------------

// Carry: one block per batch; 256 KB of F through 128 KB smem in 2 phases.
__global__ void __launch_bounds__(512)
scan_carry()
{
    __shared__ float sF[(NCHUNK / 2) * STATE];   // 128 KB

    const int b = blockIdx.x;
    const int t = threadIdx.x;
    const float* Fb = g_F + (size_t)b * NCHUNK * STATE;
    float* Hb       = g_H + (size_t)b * NCHUNK * STATE;

    float lamL = 0.f, carry = 0.f;
    if (t < STATE) {
        const float lam = g_lam[t];
        lamL = lam;
#pragma unroll
        for (int i = 0; i < 4; i++) lamL *= lamL;   // lam^16
    }

#pragma unroll
    for (int ph = 0; ph < 2; ph++) {
        __syncthreads();
#pragma unroll 4
        for (int i = t; i < (NCHUNK / 2) * STATE / 4; i += 512) {
            ((float4*)sF)[i] = ((const float4*)(Fb + ph * (NCHUNK / 2) * STATE))[i];
        }
        __syncthreads();

        if (t < STATE) {
            const int n = t;
#pragma unroll 8
            for (int c = 0; c < NCHUNK / 2; c++) {
                Hb[(ph * (NCHUNK / 2) + c) * STATE + n] = carry;
                carry = fmaf(lamL, carry, sF[c * STATE + n]);
            }
        }
    }
}

// Apply: one block per (batch, chunk); 64 threads x 4 states (float4 chains).
__global__ void __launch_bounds__(64)
scan_apply()
{
    const int b  = blockIdx.x;
    const int ch = blockIdx.y;
    const int n  = threadIdx.x * 4;

    const float4 lam4 = *(const float4*)(g_lam + n);
    float4 h = *(const float4*)(g_H + ((size_t)b * NCHUNK + ch) * STATE + n);

    const size_t m0 = (size_t)b * SEQ + (size_t)ch * CLEN;
    const float4* p = (const float4*)(g_Bu + m0 * STATE + n);
    unsigned short* oh = (unsigned short*)g_hs_hi + m0 * STATE + n;
    unsigned short* ol = (unsigned short*)g_hs_lo + m0 * STATE + n;

#pragma unroll
    for (int t = 0; t < CLEN; t++) {
        const float4 v = p[t * (STATE / 4)];
        h.x = fmaf(lam4.x, h.x, v.x);
        h.y = fmaf(lam4.y, h.y, v.y);
        h.z = fmaf(lam4.z, h.z, v.z);
        h.w = fmaf(lam4.w, h.w, v.w);
        ushort4 hh, ll;
        split_bf16(h.x, hh.x, ll.x);
        split_bf16(h.y, hh.y, ll.y);
        split_bf16(h.z, hh.z, ll.z);
        split_bf16(h.w, hh.w, ll.w);
        *(ushort4*)(oh + (size_t)t * STATE) = hh;
        *(ushort4*)(ol + (size_t)t * STATE) = ll;
    }
}

// ---------------- launch ----------------
extern "C" void kernel_launch(void* const* d_in, const int* in_sizes, int n_in,
                              void* d_out, int out_size)
{
    const float* u          = (const float*)d_in[0];
    const float* log_lambda = (const float*)d_in[1];
    const float* B_w        = (const float*)d_in[2];
    const float* C_w        = (const float*)d_in[3];
    const float* Dvec       = (const float*)d_in[4];
    float* y = (float*)d_out;

    float *Bu, *lam;
    __nv_bfloat16 *Bw_hi, *Bw_lo, *Cw_hi, *Cw_lo, *hs_hi, *hs_lo;
    cudaGetSymbolAddress((void**)&Bu,    g_Bu);
    cudaGetSymbolAddress((void**)&lam,   g_lam);
    cudaGetSymbolAddress((void**)&Bw_hi, g_Bw_hi);
    cudaGetSymbolAddress((void**)&Bw_lo, g_Bw_lo);
    cudaGetSymbolAddress((void**)&Cw_hi, g_Cw_hi);
    cudaGetSymbolAddress((void**)&Cw_lo, g_Cw_lo);
    cudaGetSymbolAddress((void**)&hs_hi, g_hs_hi);
    cudaGetSymbolAddress((void**)&hs_lo, g_hs_lo);

    const int DSMEM = 2 * (2 * 128 * 64 * 2 + 2 * 256 * 64 * 2);   // 196608
    cudaFuncSetAttribute(gemm_128x256<DMODEL, true, false, true>,
                         cudaFuncAttributeMaxDynamicSharedMemorySize, DSMEM);
    cudaFuncSetAttribute(gemm_128x256<STATE, false, true, false>,
                         cudaFuncAttributeMaxDynamicSharedMemorySize, DSMEM);
    cudaFuncSetAttribute(scan_carry, cudaFuncAttributePreferredSharedMemoryCarveout,
                         cudaSharedmemCarveoutMaxShared);

    // launch 0: split weights + lam table + D flag
    {
        int n4w = STATE * DMODEL / 4;
        split_weights<<<(2 * n4w + 255) / 256, 256>>>(
            (const float4*)B_w, (ushort4*)Bw_hi, (ushort4*)Bw_lo,
            (const float4*)C_w, (ushort4*)Cw_hi, (ushort4*)Cw_lo,
            n4w, log_lambda, Dvec);
    }

    // launch 1: GEMM1  Bu = u . B_w^T  (K=1024) + fused chunk-finals -> g_F
    gemm_128x256<DMODEL, true, false, true><<<dim3(1, MTOT / 128), 256, DSMEM>>>(
        u, nullptr, nullptr, Bw_hi, Bw_lo, Bu, STATE, nullptr, nullptr, lam);

    // launch 2: carry chain (entry states g_H), two-phase smem
    scan_carry<<<BATCH, 512>>>();

    // launch 3: apply scan -> hs; one block per chunk, float4 chains
    scan_apply<<<dim3(BATCH, NCHUNK), 64>>>();

    // launch 4: GEMM2  y = hs . C_w^T + D*u  (K=256)
    gemm_128x256<STATE, false, true, false><<<dim3(DMODEL / 256, MTOT / 128), 256, DSMEM>>>(
        nullptr, hs_hi, hs_lo, Cw_hi, Cw_lo, y, DMODEL, Dvec, u, nullptr);
}